// round 9
// baseline (speedup 1.0000x reference)
#include <cuda_runtime.h>
#include <cstdint>

#define N_NODES 100000
#define N_EDGES 1600000
#define F 128

// Scratch: H0 = X@W + b  (51.2 MB, static __device__ per allocation rules)
__device__ float g_H0[(size_t)N_NODES * F];

// ---------------------------------------------------------------------------
// GEMM: H0[N,128] = X[N,128] @ W[128,128] + b[128]
// Block: 256 threads, BM=64 rows, BK=64 k-slab. Xs reads are warp-broadcast,
// all smem stores are coalesced float4 -> conflict-free without padding.
// ---------------------------------------------------------------------------
#define BM 64
#define BK 64

__global__ __launch_bounds__(256) void gemm_kernel(const float* __restrict__ X,
                                                   const float* __restrict__ W,
                                                   const float* __restrict__ b) {
    __shared__ float Xs[BM][BK];   // 16 KB
    __shared__ float Ws[BK][F];    // 32 KB
    const int tid = threadIdx.x;
    const int tx  = tid & 31;   // output col group (4 cols)
    const int ty  = tid >> 5;   // output row group (8 rows)
    const int row0 = blockIdx.x * BM;

    float acc[8][4];
#pragma unroll
    for (int r = 0; r < 8; r++)
#pragma unroll
        for (int c = 0; c < 4; c++) acc[r][c] = 0.0f;

    for (int k0 = 0; k0 < F; k0 += BK) {
        // Load X tile: 64x64 floats = 1024 float4, 4 per thread
#pragma unroll
        for (int i = 0; i < 4; i++) {
            int idx = tid + i * 256;
            int r   = idx >> 4;      // 16 float4 per row
            int kq  = idx & 15;
            int grow = row0 + r;
            float4 v = make_float4(0.f, 0.f, 0.f, 0.f);
            if (grow < N_NODES)
                v = *(const float4*)(X + (size_t)grow * F + k0 + kq * 4);
            *(float4*)(&Xs[r][kq * 4]) = v;
        }
        // Load W tile: 64x128 floats = 2048 float4, 8 per thread
#pragma unroll
        for (int i = 0; i < 8; i++) {
            int idx = tid + i * 256;
            int kk  = idx >> 5;      // 32 float4 per row
            int jq  = idx & 31;
            *(float4*)(&Ws[kk][jq * 4]) =
                *(const float4*)(W + (size_t)(k0 + kk) * F + jq * 4);
        }
        __syncthreads();

#pragma unroll
        for (int k = 0; k < BK; k++) {
            float4 wv = *(const float4*)(&Ws[k][tx * 4]);
#pragma unroll
            for (int r = 0; r < 8; r++) {
                float a = Xs[ty * 8 + r][k];   // warp-broadcast
                acc[r][0] += a * wv.x;
                acc[r][1] += a * wv.y;
                acc[r][2] += a * wv.z;
                acc[r][3] += a * wv.w;
            }
        }
        __syncthreads();
    }

    float4 bias = *(const float4*)(b + tx * 4);
#pragma unroll
    for (int r = 0; r < 8; r++) {
        int grow = row0 + ty * 8 + r;
        if (grow < N_NODES) {
            float4 o;
            o.x = acc[r][0] + bias.x;
            o.y = acc[r][1] + bias.y;
            o.z = acc[r][2] + bias.z;
            o.w = acc[r][3] + bias.w;
            *(float4*)(g_H0 + (size_t)grow * F + tx * 4) = o;
        }
    }
}

// ---------------------------------------------------------------------------
// Edge phase: out[rows[e]] += H0[cols[e]] * vals[e]
// One warp per edge, grid-stride over edges with a fixed 4736-block grid
// (32 CTAs/SM wave structure, amortizes CTA launch overhead).
// Lane handles one float4 (gather LDG.128, scatter RED.128 via
// red.global.add.v4.f32, no return). H0 + out are L2-resident (102 < 126 MB).
// ---------------------------------------------------------------------------
#define EDGE_BLOCKS 4736
#define EDGE_WARPS_PER_BLOCK 16

__global__ __launch_bounds__(512) void edge_kernel(const int*  __restrict__ rows,
                                                   const int*  __restrict__ cols,
                                                   const float* __restrict__ vals,
                                                   float* __restrict__ out) {
    const int lane = threadIdx.x & 31;
    const int warp_global = blockIdx.x * EDGE_WARPS_PER_BLOCK + (threadIdx.x >> 5);
    const int stride = EDGE_BLOCKS * EDGE_WARPS_PER_BLOCK;

    for (int e = warp_global; e < N_EDGES; e += stride) {
        // lane 0 loads the per-edge scalars once; broadcast via shuffle
        int c = 0, r = 0; float v = 0.f;
        if (lane == 0) {
            c = __ldg(cols + e);
            r = __ldg(rows + e);
            v = __ldg(vals + e);
        }
        c = __shfl_sync(0xffffffffu, c, 0);
        r = __shfl_sync(0xffffffffu, r, 0);
        v = __shfl_sync(0xffffffffu, v, 0);

        float4 h = *(const float4*)(g_H0 + (size_t)c * F + lane * 4);
        float* dst = out + (size_t)r * F + lane * 4;
        asm volatile("red.global.add.v4.f32 [%0], {%1,%2,%3,%4};"
                     :: "l"(dst), "f"(h.x * v), "f"(h.y * v),
                        "f"(h.z * v), "f"(h.w * v)
                     : "memory");
    }
}

// ---------------------------------------------------------------------------
// ReLU + JAX dropout (threefry2x32, partitionable scheme, key=(0,42), p=0.1)
// bits[i] = x0 ^ x1 of threefry2x32((0,42), (0, i)); u = bits>>9 as [0,1);
// keep = u < 0.9f; out = keep ? relu(h)/0.9 : 0
// Key is compile-time (k0=0, k1=42): key-schedule folds to constants.
// ---------------------------------------------------------------------------
__device__ __forceinline__ uint32_t threefry_bits(uint32_t ctr) {
    constexpr uint32_t ks0 = 0u, ks1 = 42u;
    constexpr uint32_t ks2 = 0x1BD11BDAu ^ ks0 ^ ks1;
    uint32_t x0 = ks0, x1 = ctr + ks1;
#define TF_ROUND(R) { x0 += x1; x1 = __funnelshift_l(x1, x1, (R)); x1 ^= x0; }
    TF_ROUND(13) TF_ROUND(15) TF_ROUND(26) TF_ROUND(6)
    x0 += ks1; x1 += ks2 + 1u;
    TF_ROUND(17) TF_ROUND(29) TF_ROUND(16) TF_ROUND(24)
    x0 += ks2; x1 += ks0 + 2u;
    TF_ROUND(13) TF_ROUND(15) TF_ROUND(26) TF_ROUND(6)
    x0 += ks0; x1 += ks1 + 3u;
    TF_ROUND(17) TF_ROUND(29) TF_ROUND(16) TF_ROUND(24)
    x0 += ks1; x1 += ks2 + 4u;
    TF_ROUND(13) TF_ROUND(15) TF_ROUND(26) TF_ROUND(6)
    x0 += ks2; x1 += ks0 + 5u;
#undef TF_ROUND
    return x0 ^ x1;
}

__global__ __launch_bounds__(256) void finalize_kernel(float* __restrict__ out) {
    size_t i4 = (size_t)blockIdx.x * 256 + threadIdx.x;  // float4 index
    size_t base = i4 * 4;
    const size_t total = (size_t)N_NODES * F;
    if (base >= total) return;

    float4 h4 = *(float4*)(out + base);
    float res[4] = {h4.x, h4.y, h4.z, h4.w};
#pragma unroll
    for (int j = 0; j < 4; j++) {
        uint32_t bits = threefry_bits((uint32_t)(base + j));
        float u = __uint_as_float((bits >> 9) | 0x3f800000u) - 1.0f;
        float hv = fmaxf(res[j], 0.0f);
        res[j] = (u < 0.9f) ? hv * (1.0f / 0.9f) : 0.0f;
    }
    float4 o = make_float4(res[0], res[1], res[2], res[3]);
    *(float4*)(out + base) = o;
}

// ---------------------------------------------------------------------------
extern "C" void kernel_launch(void* const* d_in, const int* in_sizes, int n_in,
                              void* d_out, int out_size) {
    const float* X    = (const float*)d_in[0];
    const float* W    = (const float*)d_in[1];
    const float* b    = (const float*)d_in[2];
    const int*   rows = (const int*)  d_in[3];
    const int*   cols = (const int*)  d_in[4];
    const float* vals = (const float*)d_in[5];
    float* out = (float*)d_out;

    cudaMemsetAsync(out, 0, (size_t)out_size * sizeof(float));
    gemm_kernel<<<(N_NODES + BM - 1) / BM, 256>>>(X, W, b);
    edge_kernel<<<EDGE_BLOCKS, 512>>>(rows, cols, vals, out);
    finalize_kernel<<<((N_NODES * F / 4) + 255) / 256, 256>>>(out);
}